// round 1
// baseline (speedup 1.0000x reference)
#include <cuda_runtime.h>
#include <cuda_bf16.h>

#define FULL 0xffffffffu

// Amplitude index layout: i = (r << 5) | lane, r in [0,8), lane in [0,32).
// Qubit q lives on bit (7 - q) of i.  Bits >=5 -> register dim, bits <5 -> lane dim.

template<int B>
__device__ __forceinline__ void apply_ry(float (&sr)[8], float c, float s, int lane) {
    if constexpr (B >= 5) {
        constexpr int rb = 1 << (B - 5);
        #pragma unroll
        for (int r0 = 0; r0 < 8; r0++) {
            if (!(r0 & rb)) {
                const int r1 = r0 | rb;
                float a0 = sr[r0], a1 = sr[r1];
                sr[r0] = fmaf(c, a0, -s * a1);
                sr[r1] = fmaf(s, a0,  c * a1);
            }
        }
    } else {
        // lane dim: new = c*self + (bit ? +s : -s) * partner
        float ss = ((lane >> B) & 1) ? s : -s;
        #pragma unroll
        for (int r = 0; r < 8; r++) {
            float p = __shfl_xor_sync(FULL, sr[r], 1 << B);
            sr[r] = fmaf(ss, p, c * sr[r]);
        }
    }
}

template<int BC, int BT>
__device__ __forceinline__ void apply_cnot(float (&sr)[8], int lane) {
    if constexpr (BT >= 5) {
        constexpr int rb = 1 << (BT - 5);
        if constexpr (BC >= 5) {
            constexpr int cb = 1 << (BC - 5);
            #pragma unroll
            for (int r0 = 0; r0 < 8; r0++) {
                if ((r0 & cb) && !(r0 & rb)) {
                    const int r1 = r0 | rb;
                    float t = sr[r0]; sr[r0] = sr[r1]; sr[r1] = t;
                }
            }
        } else {
            bool ctrl = (lane >> BC) & 1;
            #pragma unroll
            for (int r0 = 0; r0 < 8; r0++) {
                if (!(r0 & rb)) {
                    const int r1 = r0 | rb;
                    float a0 = sr[r0], a1 = sr[r1];
                    sr[r0] = ctrl ? a1 : a0;
                    sr[r1] = ctrl ? a0 : a1;
                }
            }
        }
    } else {
        #pragma unroll
        for (int r = 0; r < 8; r++) {
            float p = __shfl_xor_sync(FULL, sr[r], 1 << BT);
            bool ctrl;
            if constexpr (BC >= 5) ctrl = (r >> (BC - 5)) & 1;
            else                   ctrl = (lane >> BC) & 1;
            sr[r] = ctrl ? p : sr[r];
        }
    }
}

// CRX on control bit BC, target bit BT:
// for i with ctrl bit set: new_re[i] = co*re[i] + sn*im[j], new_im[i] = co*im[i] - sn*re[j], j = i ^ (1<<BT)
template<int BC, int BT>
__device__ __forceinline__ void apply_crx(float (&sr)[8], float (&si)[8],
                                          float co, float sn, int lane) {
    if constexpr (BT >= 5) {
        constexpr int rb = 1 << (BT - 5);
        #pragma unroll
        for (int r0 = 0; r0 < 8; r0++) {
            if (!(r0 & rb)) {
                const int r1 = r0 | rb;
                float ar = sr[r0], ai = si[r0], br = sr[r1], bi = si[r1];
                float nar = fmaf(co, ar,  sn * bi);
                float nai = fmaf(co, ai, -sn * br);
                float nbr = fmaf(co, br,  sn * ai);
                float nbi = fmaf(co, bi, -sn * ar);
                if constexpr (BC >= 5) {
                    if ((r0 >> (BC - 5)) & 1) {
                        sr[r0] = nar; si[r0] = nai; sr[r1] = nbr; si[r1] = nbi;
                    }
                } else {
                    bool ctrl = (lane >> BC) & 1;
                    sr[r0] = ctrl ? nar : ar;  si[r0] = ctrl ? nai : ai;
                    sr[r1] = ctrl ? nbr : br;  si[r1] = ctrl ? nbi : bi;
                }
            }
        }
    } else {
        #pragma unroll
        for (int r = 0; r < 8; r++) {
            float pr = __shfl_xor_sync(FULL, sr[r], 1 << BT);
            float pi = __shfl_xor_sync(FULL, si[r], 1 << BT);
            bool ctrl;
            if constexpr (BC >= 5) ctrl = (r >> (BC - 5)) & 1;
            else                   ctrl = (lane >> BC) & 1;
            float nr = fmaf(co, sr[r],  sn * pi);
            float ni = fmaf(co, si[r], -sn * pr);
            sr[r] = ctrl ? nr : sr[r];
            si[r] = ctrl ? ni : si[r];
        }
    }
}

__global__ void __launch_bounds__(256)
vqc_kernel(const float* __restrict__ x,        // (B, 4, 8)
           const float* __restrict__ crx_theta, // (10,)
           const float* __restrict__ w1,        // (10, 2)
           const float* __restrict__ b1,        // (10,)
           const float* __restrict__ w2,        // (1, 10)
           const float* __restrict__ b2,        // (1,)
           float* __restrict__ out,             // (B, 1)
           int n_batch) {
    const int warp = (int)((blockIdx.x * blockDim.x + threadIdx.x) >> 5);
    const int lane = threadIdx.x & 31;
    if (warp >= n_batch) return;

    // Each lane owns one (cycle, qubit) angle: lane = cyc*8 + q.  Coalesced 128B load.
    float xa = x[warp * 32 + lane];
    float mys, myc;
    __sincosf(0.5f * xa, &mys, &myc);

    // CRX angles: lanes 0..9
    float th = __ldg(&crx_theta[lane < 10 ? lane : 0]);
    float csn, cco;
    __sincosf(0.5f * th, &csn, &cco);

    // State: real phase only needs sr.
    float sr[8], si[8];
    #pragma unroll
    for (int r = 0; r < 8; r++) sr[r] = 0.0f;
    sr[0] = (lane == 0) ? 1.0f : 0.0f;

    #pragma unroll
    for (int cyc = 0; cyc < 4; cyc++) {
        const int base = cyc * 8;
        #define RY(q) { float c = __shfl_sync(FULL, myc, base + (q)); \
                        float s = __shfl_sync(FULL, mys, base + (q)); \
                        apply_ry<7 - (q)>(sr, c, s, lane); }
        RY(0) RY(1) RY(2) RY(3) RY(4) RY(5) RY(6) RY(7)
        #undef RY
        // CNOT (q, (q+1)%8) -> bits (7-q, 7-q-1 mod)
        apply_cnot<7, 6>(sr, lane);
        apply_cnot<6, 5>(sr, lane);
        apply_cnot<5, 4>(sr, lane);
        apply_cnot<4, 3>(sr, lane);
        apply_cnot<3, 2>(sr, lane);
        apply_cnot<2, 1>(sr, lane);
        apply_cnot<1, 0>(sr, lane);
        apply_cnot<0, 7>(sr, lane);
    }

    #pragma unroll
    for (int r = 0; r < 8; r++) si[r] = 0.0f;

    // 10 CRX gates: (c,t) = (i%8, (i+1)%8) -> bits (7-c, 7-t)
    #define CRX(i, BC, BT) { float co = __shfl_sync(FULL, cco, (i)); \
                             float sn = __shfl_sync(FULL, csn, (i)); \
                             apply_crx<BC, BT>(sr, si, co, sn, lane); }
    CRX(0, 7, 6) CRX(1, 6, 5) CRX(2, 5, 4) CRX(3, 4, 3) CRX(4, 3, 2)
    CRX(5, 2, 1) CRX(6, 1, 0) CRX(7, 0, 7) CRX(8, 7, 6) CRX(9, 6, 5)
    #undef CRX

    // Probabilities + <Z> on qubit 3 (lane bit 4) and qubit 7 (lane bit 0)
    float p = 0.0f;
    #pragma unroll
    for (int r = 0; r < 8; r++) p = fmaf(sr[r], sr[r], fmaf(si[r], si[r], p));

    float f0 = (lane & 16) ? -p : p;   // qubit 3
    float f1 = (lane & 1)  ? -p : p;   // qubit 7
    #pragma unroll
    for (int off = 16; off >= 1; off >>= 1) {
        f0 += __shfl_xor_sync(FULL, f0, off);
        f1 += __shfl_xor_sync(FULL, f1, off);
    }

    // MLP: lanes 0..9 each compute one hidden unit, reduce, sigmoid on lane 0
    float contrib = 0.0f;
    if (lane < 10) {
        float z = fmaf(f0, __ldg(&w1[lane * 2 + 0]),
                  fmaf(f1, __ldg(&w1[lane * 2 + 1]), __ldg(&b1[lane])));
        float h = tanhf(z);
        contrib = h * __ldg(&w2[lane]);
    }
    #pragma unroll
    for (int off = 16; off >= 1; off >>= 1)
        contrib += __shfl_xor_sync(FULL, contrib, off);

    if (lane == 0) {
        float z = contrib + __ldg(&b2[0]);
        out[warp] = 1.0f / (1.0f + __expf(-z));
    }
}

extern "C" void kernel_launch(void* const* d_in, const int* in_sizes, int n_in,
                              void* d_out, int out_size) {
    const float* x         = (const float*)d_in[0];
    const float* crx_theta = (const float*)d_in[1];
    const float* w1        = (const float*)d_in[2];
    const float* b1        = (const float*)d_in[3];
    const float* w2        = (const float*)d_in[4];
    const float* b2        = (const float*)d_in[5];
    float* out = (float*)d_out;

    const int n_batch = in_sizes[0] / 32;           // (B,4,8) -> B
    const int threads = 256;                        // 8 warps / block
    const int blocks  = (n_batch + 7) / 8;
    vqc_kernel<<<blocks, threads>>>(x, crx_theta, w1, b1, w2, b2, out, n_batch);
}

// round 2
// speedup vs baseline: 1.3372x; 1.3372x over previous
#include <cuda_runtime.h>
#include <cuda_bf16.h>

#define FULL 0xffffffffu

// Amplitude index layout: i = (r << 5) | lane, r in [0,8), lane in [0,32).
// Qubit q lives on bit (7 - q) of i.  Bits >=5 -> register dim (bit5=r&1,
// bit6=r&2, bit7=r&4), bits <5 -> lane dim.

// CRX on control bit BC, target bit BT (unchanged from passing kernel):
template<int BC, int BT>
__device__ __forceinline__ void apply_crx(float (&sr)[8], float (&si)[8],
                                          float co, float sn, int lane) {
    if constexpr (BT >= 5) {
        constexpr int rb = 1 << (BT - 5);
        #pragma unroll
        for (int r0 = 0; r0 < 8; r0++) {
            if (!(r0 & rb)) {
                const int r1 = r0 | rb;
                float ar = sr[r0], ai = si[r0], br = sr[r1], bi = si[r1];
                float nar = fmaf(co, ar,  sn * bi);
                float nai = fmaf(co, ai, -sn * br);
                float nbr = fmaf(co, br,  sn * ai);
                float nbi = fmaf(co, bi, -sn * ar);
                if constexpr (BC >= 5) {
                    if ((r0 >> (BC - 5)) & 1) {
                        sr[r0] = nar; si[r0] = nai; sr[r1] = nbr; si[r1] = nbi;
                    }
                } else {
                    bool ctrl = (lane >> BC) & 1;
                    sr[r0] = ctrl ? nar : ar;  si[r0] = ctrl ? nai : ai;
                    sr[r1] = ctrl ? nbr : br;  si[r1] = ctrl ? nbi : bi;
                }
            }
        }
    } else {
        #pragma unroll
        for (int r = 0; r < 8; r++) {
            float pr = __shfl_xor_sync(FULL, sr[r], 1 << BT);
            float pi = __shfl_xor_sync(FULL, si[r], 1 << BT);
            bool ctrl;
            if constexpr (BC >= 5) ctrl = (r >> (BC - 5)) & 1;
            else                   ctrl = (lane >> BC) & 1;
            float nr = fmaf(co, sr[r],  sn * pi);
            float ni = fmaf(co, si[r], -sn * pr);
            sr[r] = ctrl ? nr : sr[r];
            si[r] = ctrl ? ni : si[r];
        }
    }
}

// Fused RY(bit b) then CNOT(control bit b+1 [lane], target bit b), b in {0..3}.
// t = beta? s : -s ; (alpha,gamma) = g? (-t, c) : (c, t)
template<int B>
__device__ __forceinline__ void fused_ry_cnot_lane(float (&sr)[8], float c, float s, int lane) {
    float t  = ((lane >> B) & 1) ? s : -s;
    bool  g  = (lane >> (B + 1)) & 1;
    float al = g ? -t : c;
    float ga = g ?  c : t;
    #pragma unroll
    for (int r = 0; r < 8; r++) {
        float p = __shfl_xor_sync(FULL, sr[r], 1 << B);
        sr[r] = fmaf(al, sr[r], ga * p);
    }
}

// Fused RY(bit4) then CNOT(ctrl bit5 [reg], target bit4). g = r&1 (compile time).
__device__ __forceinline__ void fused_ry4_c54(float (&sr)[8], float c, float s, int lane) {
    float t = ((lane >> 4) & 1) ? s : -s;
    #pragma unroll
    for (int r = 0; r < 8; r++) {
        float p = __shfl_xor_sync(FULL, sr[r], 16);
        if (r & 1) sr[r] = fmaf(-t, sr[r], c * p);   // g = 1
        else       sr[r] = fmaf( c, sr[r], t * p);   // g = 0
    }
}

// Fused RY(bit6) then CNOT(ctrl bit7, target bit6): pairs (r, r|2), g = r&4.
__device__ __forceinline__ void fused_ry6_c76(float (&sr)[8], float c, float s) {
    #pragma unroll
    for (int r0 = 0; r0 < 8; r0++) {
        if (!(r0 & 2)) {
            const int r1 = r0 | 2;
            float a0 = sr[r0], a1 = sr[r1];
            float n0 = fmaf(c, a0, -s * a1);
            float n1 = fmaf(s, a0,  c * a1);
            if (r0 & 4) { sr[r0] = n1; sr[r1] = n0; }   // g=1: RY then swap
            else        { sr[r0] = n0; sr[r1] = n1; }
        }
    }
}

// Fused RY(bit5) then CNOT(ctrl bit6, target bit5): pairs (r, r|1), g = r&2.
__device__ __forceinline__ void fused_ry5_c65(float (&sr)[8], float c, float s) {
    #pragma unroll
    for (int r0 = 0; r0 < 8; r0++) {
        if (!(r0 & 1)) {
            const int r1 = r0 | 1;
            float a0 = sr[r0], a1 = sr[r1];
            float n0 = fmaf(c, a0, -s * a1);
            float n1 = fmaf(s, a0,  c * a1);
            if (r0 & 2) { sr[r0] = n1; sr[r1] = n0; }
            else        { sr[r0] = n0; sr[r1] = n1; }
        }
    }
}

// Plain RY(bit7): pairs (r, r+4).
__device__ __forceinline__ void ry7_plain(float (&sr)[8], float c, float s) {
    #pragma unroll
    for (int r0 = 0; r0 < 4; r0++) {
        const int r1 = r0 + 4;
        float a0 = sr[r0], a1 = sr[r1];
        sr[r0] = fmaf(c, a0, -s * a1);
        sr[r1] = fmaf(s, a0,  c * a1);
    }
}

// Fused: previous cycle's CNOT(ctrl bit0 [lane], target bit7) then RY(bit7).
// beta=0: g? (-s,c):(c,-s)   beta=1: g? (s,c):(c,s)
__device__ __forceinline__ void fused_c07_ry7(float (&sr)[8], float c, float s, int lane) {
    bool  g   = lane & 1;
    float al0 = g ? -s : c;
    float ga0 = g ?  c : -s;
    float al1 = g ?  s : c;
    float ga1 = g ?  c : s;
    #pragma unroll
    for (int r0 = 0; r0 < 4; r0++) {
        const int r1 = r0 + 4;
        float a0 = sr[r0], a1 = sr[r1];
        sr[r0] = fmaf(al0, a0, ga0 * a1);
        sr[r1] = fmaf(al1, a1, ga1 * a0);
    }
}

__global__ void __launch_bounds__(256)
vqc_kernel(const float* __restrict__ x,         // (B, 4, 8)
           const float* __restrict__ crx_theta, // (10,)
           const float* __restrict__ w1,        // (10, 2)
           const float* __restrict__ b1,        // (10,)
           const float* __restrict__ w2,        // (1, 10)
           const float* __restrict__ b2,        // (1,)
           float* __restrict__ out,             // (B, 1)
           int n_batch) {
    const int warp = (int)((blockIdx.x * blockDim.x + threadIdx.x) >> 5);
    const int lane = threadIdx.x & 31;
    if (warp >= n_batch) return;

    // Each lane owns one (cycle, qubit) angle: lane = cyc*8 + q.
    float xa = x[warp * 32 + lane];
    float mys, myc;
    __sincosf(0.5f * xa, &mys, &myc);

    float th = __ldg(&crx_theta[lane < 10 ? lane : 0]);
    float csn, cco;
    __sincosf(0.5f * th, &csn, &cco);

    float sr[8], si[8];

    // ---------------- Cycle 0: closed-form construction ----------------
    // After 8 RYs on |0>, state is a product; the CNOT chain is the GF(2)
    // map B with rows: g0=x0^x1 g1=x1^x2 g2=x2^x3 g3=x3^x4 g4=x4^x5
    // g5=x5^x6 g6=x0^x6^x7 g7=x0^x7.  amp[i] = prod_b F_b(g_b(i)),
    // F_b(beta) = beta ? sin(q=7-b) : cos(q=7-b).
    {
        float cq0 = __shfl_sync(FULL, myc, 0), sq0 = __shfl_sync(FULL, mys, 0);
        float cq1 = __shfl_sync(FULL, myc, 1), sq1 = __shfl_sync(FULL, mys, 1);
        float cq2 = __shfl_sync(FULL, myc, 2), sq2 = __shfl_sync(FULL, mys, 2);
        float cq3 = __shfl_sync(FULL, myc, 3), sq3 = __shfl_sync(FULL, mys, 3);
        float cq4 = __shfl_sync(FULL, myc, 4), sq4 = __shfl_sync(FULL, mys, 4);
        float cq5 = __shfl_sync(FULL, myc, 5), sq5 = __shfl_sync(FULL, mys, 5);
        float cq6 = __shfl_sync(FULL, myc, 6), sq6 = __shfl_sync(FULL, mys, 6);
        float cq7 = __shfl_sync(FULL, myc, 7), sq7 = __shfl_sync(FULL, mys, 7);

        const int x0 =  lane       & 1;
        const int x1 = (lane >> 1) & 1;
        const int x2 = (lane >> 2) & 1;
        const int x3 = (lane >> 3) & 1;
        const int x4 = (lane >> 4) & 1;

        float F0 = (x0 ^ x1) ? sq7 : cq7;
        float F1 = (x1 ^ x2) ? sq6 : cq6;
        float F2 = (x2 ^ x3) ? sq5 : cq5;
        float F3 = (x3 ^ x4) ? sq4 : cq4;
        float Plane = (F0 * F1) * (F2 * F3);

        float f4_0 = x4 ? sq3 : cq3;   // bit5 = 0
        float f4_1 = x4 ? cq3 : sq3;   // bit5 = 1
        float f6_0 = x0 ? sq1 : cq1;   // (bit6^bit7) = 0
        float f6_1 = x0 ? cq1 : sq1;
        float f7_0 = x0 ? sq0 : cq0;   // bit7 = 0
        float f7_1 = x0 ? cq0 : sq0;

        #pragma unroll
        for (int r = 0; r < 8; r++) {
            const int b5 =  r       & 1;
            const int b6 = (r >> 1) & 1;
            const int b7 = (r >> 2) & 1;
            float F4 = b5 ? f4_1 : f4_0;
            float F5 = (b5 ^ b6) ? sq2 : cq2;
            float F6 = (b6 ^ b7) ? f6_1 : f6_0;
            float F7 = b7 ? f7_1 : f7_0;
            sr[r] = (Plane * F4) * (F5 * F6) * F7;
        }
    }

    // ---------------- Cycles 1..3: fused RY+CNOT gates ----------------
    #pragma unroll
    for (int k = 1; k < 4; k++) {
        const int k8 = k * 8;
        float cg, sg;
        // gate on bit b uses qubit q = 7-b -> angle lane k8 + 7 - b
        cg = __shfl_sync(FULL, myc, k8 + 0); sg = __shfl_sync(FULL, mys, k8 + 0);
        if (k == 1) ry7_plain(sr, cg, sg);           // cycle0 CNOTs absorbed in closed form
        else        fused_c07_ry7(sr, cg, sg, lane); // carries prev cycle's CNOT(0,7)

        cg = __shfl_sync(FULL, myc, k8 + 1); sg = __shfl_sync(FULL, mys, k8 + 1);
        fused_ry6_c76(sr, cg, sg);
        cg = __shfl_sync(FULL, myc, k8 + 2); sg = __shfl_sync(FULL, mys, k8 + 2);
        fused_ry5_c65(sr, cg, sg);
        cg = __shfl_sync(FULL, myc, k8 + 3); sg = __shfl_sync(FULL, mys, k8 + 3);
        fused_ry4_c54(sr, cg, sg, lane);
        cg = __shfl_sync(FULL, myc, k8 + 4); sg = __shfl_sync(FULL, mys, k8 + 4);
        fused_ry_cnot_lane<3>(sr, cg, sg, lane);
        cg = __shfl_sync(FULL, myc, k8 + 5); sg = __shfl_sync(FULL, mys, k8 + 5);
        fused_ry_cnot_lane<2>(sr, cg, sg, lane);
        cg = __shfl_sync(FULL, myc, k8 + 6); sg = __shfl_sync(FULL, mys, k8 + 6);
        fused_ry_cnot_lane<1>(sr, cg, sg, lane);
        cg = __shfl_sync(FULL, myc, k8 + 7); sg = __shfl_sync(FULL, mys, k8 + 7);
        fused_ry_cnot_lane<0>(sr, cg, sg, lane);
    }

    // Cycle 3's trailing CNOT(ctrl bit0, target bit7): conditional reg swap.
    {
        bool g = lane & 1;
        #pragma unroll
        for (int r0 = 0; r0 < 4; r0++) {
            float a0 = sr[r0], a1 = sr[r0 + 4];
            sr[r0]     = g ? a1 : a0;
            sr[r0 + 4] = g ? a0 : a1;
        }
    }

    #pragma unroll
    for (int r = 0; r < 8; r++) si[r] = 0.0f;

    // 10 CRX gates: (c,t) = (i%8, (i+1)%8) -> bits (7-c, 7-t)
    #define CRX(i, BC, BT) { float co = __shfl_sync(FULL, cco, (i)); \
                             float sn = __shfl_sync(FULL, csn, (i)); \
                             apply_crx<BC, BT>(sr, si, co, sn, lane); }
    CRX(0, 7, 6) CRX(1, 6, 5) CRX(2, 5, 4) CRX(3, 4, 3) CRX(4, 3, 2)
    CRX(5, 2, 1) CRX(6, 1, 0) CRX(7, 0, 7) CRX(8, 7, 6) CRX(9, 6, 5)
    #undef CRX

    // Probabilities + <Z> on qubit 3 (lane bit 4) and qubit 7 (lane bit 0)
    float p = 0.0f;
    #pragma unroll
    for (int r = 0; r < 8; r++) p = fmaf(sr[r], sr[r], fmaf(si[r], si[r], p));

    float f0 = (lane & 16) ? -p : p;   // qubit 3
    float f1 = (lane & 1)  ? -p : p;   // qubit 7
    #pragma unroll
    for (int off = 16; off >= 1; off >>= 1) {
        f0 += __shfl_xor_sync(FULL, f0, off);
        f1 += __shfl_xor_sync(FULL, f1, off);
    }

    // MLP: lanes 0..9 each compute one hidden unit, reduce, sigmoid on lane 0
    float contrib = 0.0f;
    if (lane < 10) {
        float z = fmaf(f0, __ldg(&w1[lane * 2 + 0]),
                  fmaf(f1, __ldg(&w1[lane * 2 + 1]), __ldg(&b1[lane])));
        float h = tanhf(z);
        contrib = h * __ldg(&w2[lane]);
    }
    #pragma unroll
    for (int off = 16; off >= 1; off >>= 1)
        contrib += __shfl_xor_sync(FULL, contrib, off);

    if (lane == 0) {
        float z = contrib + __ldg(&b2[0]);
        out[warp] = 1.0f / (1.0f + __expf(-z));
    }
}

extern "C" void kernel_launch(void* const* d_in, const int* in_sizes, int n_in,
                              void* d_out, int out_size) {
    const float* x         = (const float*)d_in[0];
    const float* crx_theta = (const float*)d_in[1];
    const float* w1        = (const float*)d_in[2];
    const float* b1        = (const float*)d_in[3];
    const float* w2        = (const float*)d_in[4];
    const float* b2        = (const float*)d_in[5];
    float* out = (float*)d_out;

    const int n_batch = in_sizes[0] / 32;           // (B,4,8) -> B
    const int threads = 256;                        // 8 warps / block
    const int blocks  = (n_batch + 7) / 8;
    vqc_kernel<<<blocks, threads>>>(x, crx_theta, w1, b1, w2, b2, out, n_batch);
}

// round 3
// speedup vs baseline: 1.5936x; 1.1918x over previous
#include <cuda_runtime.h>
#include <cuda_bf16.h>

#define FULL 0xffffffffu

// Layout B: 2 batch elements per warp.  Element = lane>>4 (16 lanes each).
// Amplitude index i (8 bits): bits 0-3 = lane bits 0-3, bits 4-7 = reg bits 0-3
// (16 float registers per element).  Qubit q lives on bit (7-q).

// Fused RY(lane bit B) + CNOT(ctrl lane bit B+1, target bit B), B in {0,1,2}.
template<int B>
__device__ __forceinline__ void fused_lane(float (&sr)[16], float c, float s, int lane) {
    float t  = ((lane >> B) & 1) ? s : -s;
    bool  g  = (lane >> (B + 1)) & 1;
    float al = g ? -t : c;
    float ga = g ?  c : t;
    #pragma unroll
    for (int r = 0; r < 16; r++) {
        float p = __shfl_xor_sync(FULL, sr[r], 1 << B);
        sr[r] = fmaf(al, sr[r], ga * p);
    }
}

// Fused RY(reg bit TB) + CNOT(ctrl reg bit TB+1, target TB), TB in {0,1,2}.
template<int TB>
__device__ __forceinline__ void fused_reg(float (&sr)[16], float c, float s) {
    constexpr int tb = 1 << TB;
    constexpr int cb = 1 << (TB + 1);
    #pragma unroll
    for (int r0 = 0; r0 < 16; r0++) {
        if (!(r0 & tb)) {
            const int r1 = r0 | tb;
            float a0 = sr[r0], a1 = sr[r1];
            float n0 = fmaf(c, a0, -s * a1);
            float n1 = fmaf(s, a0,  c * a1);
            if (r0 & cb) { sr[r0] = n1; sr[r1] = n0; }   // CNOT swap after RY
            else         { sr[r0] = n0; sr[r1] = n1; }
        }
    }
}

__global__ void __launch_bounds__(256)
vqc_kernel(const float* __restrict__ x,         // (B, 4, 8)
           const float* __restrict__ crx_theta, // (10,)
           const float* __restrict__ w1,        // (10, 2)
           const float* __restrict__ b1,        // (10,)
           const float* __restrict__ w2,        // (1, 10)
           const float* __restrict__ b2,        // (1,)
           float* __restrict__ out,             // (B, 1)
           int n_batch) {
    const int pair = (int)((blockIdx.x * blockDim.x + threadIdx.x) >> 5);
    const int lane = threadIdx.x & 31;
    const int e0   = pair * 2;
    if (e0 >= n_batch) return;
    const int half = lane & 16;      // 0 for element 0, 16 for element 1
    const int lo   = lane & 15;

    // Angle registers: P holds angles[0..15] of each element in its half,
    // Q holds angles[16..31].  off = (lane&15) | ((lane&16)<<1).
    const bool has1 = (e0 + 1) < n_batch;
    const int  off  = (half && !has1) ? lo : (lo | (half << 1));
    const float* xb = x + (size_t)e0 * 32;
    float aP = xb[off];
    float aQ = xb[off + 16];
    float Pc, Ps, Qc, Qs;
    __sincosf(0.5f * aP, &Ps, &Pc);
    __sincosf(0.5f * aQ, &Qs, &Qc);

    // CRX angles are batch-uniform: lanes 0..9 hold them; both halves identical.
    float th = __ldg(&crx_theta[lo < 10 ? lo : 0]);
    float csn, cco;
    __sincosf(0.5f * th, &csn, &cco);

    float sr[16], si[16];

    // ---------------- Cycle 0: closed form ----------------
    // amp[i] = prod_b F_b(v_b(i)); v rows: v0=x0^x1 v1=x1^x2 v2=x2^x3 v3=x3^b4
    // v4=b4^b5 v5=b5^b6 v6=x0^b6^b7 v7=x0^b7;  F_b selects (cos,sin) of qubit 7-b.
    {
        float cq[8], sq[8];
        #pragma unroll
        for (int q = 0; q < 8; q++) {
            cq[q] = __shfl_sync(FULL, Pc, half | q);
            sq[q] = __shfl_sync(FULL, Ps, half | q);
        }
        const int x0 = lane & 1, x1 = (lane >> 1) & 1, x2 = (lane >> 2) & 1, x3 = (lane >> 3) & 1;
        float F0 = (x0 ^ x1) ? sq[7] : cq[7];
        float F1 = (x1 ^ x2) ? sq[6] : cq[6];
        float F2 = (x2 ^ x3) ? sq[5] : cq[5];
        float Plane = F0 * F1 * F2;
        float f3_0 = x3 ? sq[4] : cq[4];
        float f3_1 = x3 ? cq[4] : sq[4];
        float f6_0 = x0 ? sq[1] : cq[1];
        float f6_1 = x0 ? cq[1] : sq[1];
        float f7_0 = x0 ? sq[0] : cq[0];
        float f7_1 = x0 ? cq[0] : sq[0];
        float P0 = Plane * f3_0, P1 = Plane * f3_1;
        #pragma unroll
        for (int r = 0; r < 16; r++) {
            const int b4 = r & 1, b5 = (r >> 1) & 1, b6 = (r >> 2) & 1, b7 = (r >> 3) & 1;
            float t = b4 ? P1 : P0;
            t *= (b4 ^ b5) ? sq[3] : cq[3];
            t *= (b5 ^ b6) ? sq[2] : cq[2];
            t *= (b6 ^ b7) ? f6_1 : f6_0;
            t *= b7 ? f7_1 : f7_0;
            sr[r] = t;
        }
    }

    // ---------------- Cycles 1..3: fused RY+CNOT ----------------
    #pragma unroll
    for (int k = 1; k < 4; k++) {
        float c_, s_;
        #define BCAST(q) { const int j = k * 8 + (q);                                  \
            if (j < 16) { c_ = __shfl_sync(FULL, Pc, half | j);                        \
                          s_ = __shfl_sync(FULL, Ps, half | j); }                      \
            else        { c_ = __shfl_sync(FULL, Qc, half | (j - 16));                 \
                          s_ = __shfl_sync(FULL, Qs, half | (j - 16)); } }

        // b=7 (q=0): reg pairs (r, r+8); k>=2 fused with prev cycle's CNOT(0,7)
        BCAST(0)
        if (k == 1) {
            #pragma unroll
            for (int r0 = 0; r0 < 8; r0++) {
                float a0 = sr[r0], a1 = sr[r0 + 8];
                sr[r0]     = fmaf(c_, a0, -s_ * a1);
                sr[r0 + 8] = fmaf(s_, a0,  c_ * a1);
            }
        } else {
            bool  g   = lane & 1;
            float al0 = g ? -s_ : c_, ga0 = g ? c_ : -s_;
            float al1 = g ?  s_ : c_, ga1 = g ? c_ :  s_;
            #pragma unroll
            for (int r0 = 0; r0 < 8; r0++) {
                float a0 = sr[r0], a1 = sr[r0 + 8];
                sr[r0]     = fmaf(al0, a0, ga0 * a1);
                sr[r0 + 8] = fmaf(al1, a1, ga1 * a0);
            }
        }
        BCAST(1) fused_reg<2>(sr, c_, s_);   // b=6, ctrl bit7
        BCAST(2) fused_reg<1>(sr, c_, s_);   // b=5, ctrl bit6
        BCAST(3) fused_reg<0>(sr, c_, s_);   // b=4, ctrl bit5
        // b=3 (q=4): lane mask 8, ctrl = reg bit0
        BCAST(4)
        {
            float t = ((lane >> 3) & 1) ? s_ : -s_;
            #pragma unroll
            for (int r = 0; r < 16; r++) {
                float p = __shfl_xor_sync(FULL, sr[r], 8);
                if (r & 1) sr[r] = fmaf(-t, sr[r], c_ * p);
                else       sr[r] = fmaf( c_, sr[r], t  * p);
            }
        }
        BCAST(5) fused_lane<2>(sr, c_, s_, lane);   // b=2, ctrl lane bit3
        BCAST(6) fused_lane<1>(sr, c_, s_, lane);   // b=1, ctrl lane bit2
        BCAST(7) fused_lane<0>(sr, c_, s_, lane);   // b=0, ctrl lane bit1
        #undef BCAST
    }
    // Cycle 3's trailing CNOT(0,7): swap (r, r+8) where lane bit0 set
    {
        bool g = lane & 1;
        #pragma unroll
        for (int r0 = 0; r0 < 8; r0++) {
            float a0 = sr[r0], a1 = sr[r0 + 8];
            sr[r0]     = g ? a1 : a0;
            sr[r0 + 8] = g ? a0 : a1;
        }
    }

    #pragma unroll
    for (int r = 0; r < 16; r++) si[r] = 0.0f;

    // ---------------- 10 CRX gates ----------------
    #define CBC(i) const float co = __shfl_sync(FULL, cco, (i)); \
                   const float sn = __shfl_sync(FULL, csn, (i));
    #define CRX_PAIR_FULL(A, Bq) {                                        \
        float ar = sr[A], ai = si[A], br = sr[Bq], bi = si[Bq];           \
        sr[A]  = fmaf(co, ar,  sn * bi); si[A]  = fmaf(co, ai, -sn * br); \
        sr[Bq] = fmaf(co, br,  sn * ai); si[Bq] = fmaf(co, bi, -sn * ar); }
    #define CRX_PAIR_RE(A, Bq) {                              \
        float ar = sr[A], br = sr[Bq];                        \
        sr[A]  = co * ar;  si[A]  = -sn * br;                 \
        sr[Bq] = co * br;  si[Bq] = -sn * ar; }

    // CRX0: ctrl reg bit3, target reg bit2 (si==0 everywhere -> real fast path)
    { CBC(0)
      CRX_PAIR_RE(8, 12) CRX_PAIR_RE(9, 13) CRX_PAIR_RE(10, 14) CRX_PAIR_RE(11, 15) }
    // CRX1: ctrl reg bit2, target reg bit1
    { CBC(1)
      CRX_PAIR_RE(4, 6) CRX_PAIR_RE(5, 7)           // si still 0 on regs 4-7
      CRX_PAIR_FULL(12, 14) CRX_PAIR_FULL(13, 15) }
    // CRX2: ctrl reg bit1, target reg bit0
    { CBC(2)
      CRX_PAIR_RE(2, 3)                              // si still 0 on regs 2,3
      CRX_PAIR_FULL(6, 7) CRX_PAIR_FULL(10, 11) CRX_PAIR_FULL(14, 15) }
    // CRX3: ctrl reg bit0, target lane bit3 (odd regs only; si[1]==0 -> 1 shfl)
    { CBC(3)
      { float pr = __shfl_xor_sync(FULL, sr[1], 8);
        float nr = co * sr[1];
        si[1] = -sn * pr;
        sr[1] = nr; }
      #pragma unroll
      for (int r = 3; r < 16; r += 2) {
          float pr = __shfl_xor_sync(FULL, sr[r], 8);
          float pi = __shfl_xor_sync(FULL, si[r], 8);
          float nr = fmaf(co, sr[r],  sn * pi);
          float ni = fmaf(co, si[r], -sn * pr);
          sr[r] = nr; si[r] = ni;
      } }
    // CRX4: ctrl lane bit3, target lane bit2 (fold ctrl; si[0]==0 -> skip 1 shfl)
    { CBC(4)
      bool  g    = (lane >> 3) & 1;
      float co_e = g ? co : 1.0f;
      float sn_e = g ? sn : 0.0f;
      { float pr = __shfl_xor_sync(FULL, sr[0], 4);
        float nr = co_e * sr[0];
        si[0] = -sn_e * pr;
        sr[0] = nr; }
      #pragma unroll
      for (int r = 1; r < 16; r++) {
          float pr = __shfl_xor_sync(FULL, sr[r], 4);
          float pi = __shfl_xor_sync(FULL, si[r], 4);
          float nr = fmaf(co_e, sr[r],  sn_e * pi);
          float ni = fmaf(co_e, si[r], -sn_e * pr);
          sr[r] = nr; si[r] = ni;
      } }
    // CRX5: ctrl lane bit2, target lane bit1
    { CBC(5)
      bool  g    = (lane >> 2) & 1;
      float co_e = g ? co : 1.0f;
      float sn_e = g ? sn : 0.0f;
      #pragma unroll
      for (int r = 0; r < 16; r++) {
          float pr = __shfl_xor_sync(FULL, sr[r], 2);
          float pi = __shfl_xor_sync(FULL, si[r], 2);
          float nr = fmaf(co_e, sr[r],  sn_e * pi);
          float ni = fmaf(co_e, si[r], -sn_e * pr);
          sr[r] = nr; si[r] = ni;
      } }
    // CRX6: ctrl lane bit1, target lane bit0
    { CBC(6)
      bool  g    = (lane >> 1) & 1;
      float co_e = g ? co : 1.0f;
      float sn_e = g ? sn : 0.0f;
      #pragma unroll
      for (int r = 0; r < 16; r++) {
          float pr = __shfl_xor_sync(FULL, sr[r], 1);
          float pi = __shfl_xor_sync(FULL, si[r], 1);
          float nr = fmaf(co_e, sr[r],  sn_e * pi);
          float ni = fmaf(co_e, si[r], -sn_e * pr);
          sr[r] = nr; si[r] = ni;
      } }
    // CRX7: ctrl lane bit0, target reg bit3 (fold ctrl into coefficients)
    { CBC(7)
      bool  g    = lane & 1;
      float co_e = g ? co : 1.0f;
      float sn_e = g ? sn : 0.0f;
      #pragma unroll
      for (int r0 = 0; r0 < 8; r0++) {
          const int r1 = r0 + 8;
          float ar = sr[r0], ai = si[r0], br = sr[r1], bi = si[r1];
          sr[r0] = fmaf(co_e, ar,  sn_e * bi);  si[r0] = fmaf(co_e, ai, -sn_e * br);
          sr[r1] = fmaf(co_e, br,  sn_e * ai);  si[r1] = fmaf(co_e, bi, -sn_e * ar);
      } }
    // CRX8: ctrl reg bit3, target reg bit2
    { CBC(8)
      CRX_PAIR_FULL(8, 12) CRX_PAIR_FULL(9, 13) CRX_PAIR_FULL(10, 14) CRX_PAIR_FULL(11, 15) }
    // CRX9: ctrl reg bit2, target reg bit1
    { CBC(9)
      CRX_PAIR_FULL(4, 6) CRX_PAIR_FULL(5, 7) CRX_PAIR_FULL(12, 14) CRX_PAIR_FULL(13, 15) }
    #undef CBC
    #undef CRX_PAIR_FULL
    #undef CRX_PAIR_RE

    // ---------------- Measurement + MLP ----------------
    // qubit3 = bit4 = reg bit0 (sign per reg), qubit7 = bit0 = lane bit0.
    float S0 = 0.0f, S1 = 0.0f;
    #pragma unroll
    for (int r = 0; r < 16; r += 2) {
        S0 = fmaf(sr[r],     sr[r],     fmaf(si[r],     si[r],     S0));
        S1 = fmaf(sr[r + 1], sr[r + 1], fmaf(si[r + 1], si[r + 1], S1));
    }
    float f0  = S0 - S1;
    float tot = S0 + S1;
    float f1  = (lane & 1) ? -tot : tot;
    #pragma unroll
    for (int m = 8; m >= 1; m >>= 1) {
        f0 += __shfl_xor_sync(FULL, f0, m);
        f1 += __shfl_xor_sync(FULL, f1, m);
    }

    float contrib = 0.0f;
    if (lo < 10) {
        float z = fmaf(f0, __ldg(&w1[lo * 2 + 0]),
                  fmaf(f1, __ldg(&w1[lo * 2 + 1]), __ldg(&b1[lo])));
        contrib = tanhf(z) * __ldg(&w2[lo]);
    }
    #pragma unroll
    for (int m = 8; m >= 1; m >>= 1)
        contrib += __shfl_xor_sync(FULL, contrib, m);

    if (lo == 0) {
        const int e = e0 + (half >> 4);
        if (e < n_batch) {
            float z = contrib + __ldg(&b2[0]);
            out[e] = 1.0f / (1.0f + __expf(-z));
        }
    }
}

extern "C" void kernel_launch(void* const* d_in, const int* in_sizes, int n_in,
                              void* d_out, int out_size) {
    const float* x         = (const float*)d_in[0];
    const float* crx_theta = (const float*)d_in[1];
    const float* w1        = (const float*)d_in[2];
    const float* b1        = (const float*)d_in[3];
    const float* w2        = (const float*)d_in[4];
    const float* b2        = (const float*)d_in[5];
    float* out = (float*)d_out;

    const int n_batch = in_sizes[0] / 32;      // (B,4,8) -> B
    const int pairs   = (n_batch + 1) / 2;
    const int threads = 256;                   // 8 warps (16 elements) per block
    const int blocks  = (pairs + 7) / 8;
    vqc_kernel<<<blocks, threads>>>(x, crx_theta, w1, b1, w2, b2, out, n_batch);
}

// round 4
// speedup vs baseline: 1.7716x; 1.1117x over previous
#include <cuda_runtime.h>
#include <cuda_bf16.h>

#define FULL 0xffffffffu
typedef unsigned long long u64;

// Packed f32x2 primitives (sm_103a FFMA2 path, PTX-only)
#define MK2(d, lo, hi)   asm("mov.b64 %0, {%1, %2};" : "=l"(d) : "f"(lo), "f"(hi))
#define UP2(lo, hi, s)   asm("mov.b64 {%0, %1}, %2;" : "=f"(lo), "=f"(hi) : "l"(s))
#define PMUL(d, a, b)    asm("mul.rn.f32x2 %0, %1, %2;" : "=l"(d) : "l"(a), "l"(b))
#define PFMA(d, a, b, c) asm("fma.rn.f32x2 %0, %1, %2, %3;" : "=l"(d) : "l"(a), "l"(b), "l"(c))

__device__ __forceinline__ u64 paxpby(u64 A, u64 X, u64 B, u64 Y) {
    u64 t, d; PMUL(t, B, Y); PFMA(d, A, X, t); return d;
}
__device__ __forceinline__ u64 dup2(float v) { u64 d; MK2(d, v, v); return d; }

// Layout: 2 batch elements per warp (16 lanes each; element = lane>>4).
// Amplitude index i: bits 0-3 = lane bits, bits 4-7 = register bits.
// Register bit0 = slot within a 64-bit pack (packs srp[0..7]); pack index j
// carries reg bits 1-3 (i bits 5-7).  Qubit q lives on amplitude bit (7-q).

__global__ void __launch_bounds__(256)
vqc_kernel(const float* __restrict__ x,         // (B, 4, 8)
           const float* __restrict__ crx_theta, // (10,)
           const float* __restrict__ w1,        // (10, 2)
           const float* __restrict__ b1,        // (10,)
           const float* __restrict__ w2,        // (1, 10)
           const float* __restrict__ b2,        // (1,)
           float* __restrict__ out,             // (B, 1)
           int n_batch) {
    const int pair = (int)((blockIdx.x * blockDim.x + threadIdx.x) >> 5);
    const int lane = threadIdx.x & 31;
    const int e0   = pair * 2;
    if (e0 >= n_batch) return;
    const int half = lane & 16;
    const int lo   = lane & 15;

    const bool has1 = (e0 + 1) < n_batch;
    const int  off  = (half && !has1) ? lo : (lo | (half << 1));
    const float* xb = x + (size_t)e0 * 32;
    float aP = xb[off];
    float aQ = xb[off + 16];
    float Pc, Ps, Qc, Qs;
    __sincosf(0.5f * aP, &Ps, &Pc);
    __sincosf(0.5f * aQ, &Qs, &Qc);

    float th = __ldg(&crx_theta[lo < 10 ? lo : 0]);
    float csn, cco;
    __sincosf(0.5f * th, &csn, &cco);

    u64 srp[8], sip[8];

    // ---------------- Cycle 0: closed form ----------------
    {
        float cq[8], sq[8];
        #pragma unroll
        for (int q = 0; q < 8; q++) {
            cq[q] = __shfl_sync(FULL, Pc, half | q);
            sq[q] = __shfl_sync(FULL, Ps, half | q);
        }
        const int x0 = lane & 1, x1 = (lane >> 1) & 1, x2 = (lane >> 2) & 1, x3 = (lane >> 3) & 1;
        float F0 = (x0 ^ x1) ? sq[7] : cq[7];
        float F1 = (x1 ^ x2) ? sq[6] : cq[6];
        float F2 = (x2 ^ x3) ? sq[5] : cq[5];
        float Plane = F0 * F1 * F2;
        float PB0 = Plane * (x3 ? sq[4] : cq[4]);
        float PB1 = Plane * (x3 ? cq[4] : sq[4]);
        float f6_0 = x0 ? sq[1] : cq[1];
        float f6_1 = x0 ? cq[1] : sq[1];
        float f7_0 = x0 ? sq[0] : cq[0];
        float f7_1 = x0 ? cq[0] : sq[0];
        // G(b5) = per-slot base: slot x (b4=0), slot y (b4=1)
        float G0x = PB0 * cq[3], G0y = PB1 * sq[3];
        float G1x = PB0 * sq[3], G1y = PB1 * cq[3];
        #pragma unroll
        for (int j = 0; j < 8; j++) {
            const int b5 = j & 1, b6 = (j >> 1) & 1, b7 = (j >> 2) & 1;
            float w = ((b5 ^ b6) ? sq[2] : cq[2])
                    * ((b6 ^ b7) ? f6_1 : f6_0)
                    * (b7 ? f7_1 : f7_0);
            float l_ = (b5 ? G1x : G0x) * w;
            float h_ = (b5 ? G1y : G0y) * w;
            MK2(srp[j], l_, h_);
        }
    }

    // ---------------- Cycles 1..3: fused RY+CNOT ----------------
    #pragma unroll
    for (int k = 1; k < 4; k++) {
        float c_, s_;
        #define BCAST(q) { const int j_ = k * 8 + (q);                                 \
            if (j_ < 16) { c_ = __shfl_sync(FULL, Pc, half | j_);                      \
                           s_ = __shfl_sync(FULL, Ps, half | j_); }                    \
            else         { c_ = __shfl_sync(FULL, Qc, half | (j_ - 16));               \
                           s_ = __shfl_sync(FULL, Qs, half | (j_ - 16)); } }

        // ---- bit7 gate (packs j <-> j+4), k>=2 fused with prev CNOT(0,7) ----
        BCAST(0)
        if (k == 1) {
            u64 CC = dup2(c_), SS = dup2(s_), NS = dup2(-s_);
            #pragma unroll
            for (int j = 0; j < 4; j++) {
                u64 a = srp[j], b = srp[j + 4];
                srp[j]     = paxpby(CC, a, NS, b);
                srp[j + 4] = paxpby(SS, a, CC, b);
            }
        } else {
            bool g = lane & 1;
            u64 AL0 = dup2(g ? -s_ : c_), GA0 = dup2(g ? c_ : -s_);
            u64 AL1 = dup2(g ?  s_ : c_), GA1 = dup2(g ? c_ :  s_);
            #pragma unroll
            for (int j = 0; j < 4; j++) {
                u64 a = srp[j], b = srp[j + 4];
                srp[j]     = paxpby(AL0, a, GA0, b);
                srp[j + 4] = paxpby(AL1, b, GA1, a);
            }
        }
        // ---- bit6 gate: pack pairs (j, j|2), CNOT swap if j&4 ----
        BCAST(1)
        {
            u64 CC = dup2(c_), SS = dup2(s_), NS = dup2(-s_);
            #pragma unroll
            for (int j = 0; j < 8; j++) {
                if (!(j & 2)) {
                    const int j2 = j | 2;
                    u64 a = srp[j], b = srp[j2];
                    u64 n0 = paxpby(CC, a, NS, b);
                    u64 n1 = paxpby(SS, a, CC, b);
                    if (j & 4) { srp[j] = n1; srp[j2] = n0; }
                    else       { srp[j] = n0; srp[j2] = n1; }
                }
            }
        }
        // ---- bit5 gate: pack pairs (j, j|1), swap if j&2 ----
        BCAST(2)
        {
            u64 CC = dup2(c_), SS = dup2(s_), NS = dup2(-s_);
            #pragma unroll
            for (int j = 0; j < 8; j += 2) {
                const int j1 = j | 1;
                u64 a = srp[j], b = srp[j1];
                u64 n0 = paxpby(CC, a, NS, b);
                u64 n1 = paxpby(SS, a, CC, b);
                if (j & 2) { srp[j] = n1; srp[j1] = n0; }
                else       { srp[j] = n0; srp[j1] = n1; }
            }
        }
        // ---- bit4 gate (within pack), swap if j&1: reversed-operand packed ----
        BCAST(3)
        {
            u64 CC; MK2(CC, c_, c_);
            u64 SV; MK2(SV, -s_, s_);   // no-swap:  out = CC*a + SV*rev
            u64 SW; MK2(SW, s_, -s_);   // swap:     out = CC*rev + SW*a
            #pragma unroll
            for (int j = 0; j < 8; j++) {
                float a0, a1; UP2(a0, a1, srp[j]);
                u64 rv; MK2(rv, a1, a0);
                if (j & 1) srp[j] = paxpby(CC, rv, SW, srp[j]);
                else       srp[j] = paxpby(CC, srp[j], SV, rv);
            }
        }
        // ---- bit3 gate: lane mask 8, ctrl = slot parity (reg bit0) ----
        BCAST(4)
        {
            float t = ((lane >> 3) & 1) ? s_ : -s_;
            u64 ALv; MK2(ALv, c_, -t);
            u64 GAv; MK2(GAv, t, c_);
            #pragma unroll
            for (int j = 0; j < 8; j++) {
                u64 p = __shfl_xor_sync(FULL, srp[j], 8);
                srp[j] = paxpby(ALv, srp[j], GAv, p);
            }
        }
        // ---- lane gates: bit2 (ctrl lane3), bit1 (ctrl lane2), bit0 (ctrl lane1) ----
        #define LGATE(B) {                                                   \
            float t = ((lane >> (B)) & 1) ? s_ : -s_;                        \
            bool  g = (lane >> ((B) + 1)) & 1;                               \
            u64 AL = dup2(g ? -t : c_);                                      \
            u64 GA = dup2(g ?  c_ : t);                                      \
            _Pragma("unroll")                                                \
            for (int j = 0; j < 8; j++) {                                    \
                u64 p = __shfl_xor_sync(FULL, srp[j], 1 << (B));             \
                srp[j] = paxpby(AL, srp[j], GA, p);                          \
            } }
        BCAST(5) LGATE(2)
        BCAST(6) LGATE(1)
        BCAST(7) LGATE(0)
        #undef LGATE
        #undef BCAST
    }
    // Cycle 3's trailing CNOT(0,7): conditional pack swap (j <-> j+4)
    {
        bool g = lane & 1;
        #pragma unroll
        for (int j = 0; j < 4; j++) {
            u64 a = srp[j], b = srp[j + 4];
            srp[j]     = g ? b : a;
            srp[j + 4] = g ? a : b;
        }
    }

    // Only si pack0 (regs 0,1) is read before written in the CRX chain.
    { float z0 = 0.0f; MK2(sip[0], z0, z0); }

    // ---------------- 10 CRX gates ----------------
    #define CBC(i) const float co = __shfl_sync(FULL, cco, (i)); \
                   const float sn = __shfl_sync(FULL, csn, (i));

    // CRX0: ctrl reg bit3, tgt reg bit2 -> pack pairs (4,6),(5,7); si==0 (RE)
    { CBC(0)
      u64 CO = dup2(co), NSN = dup2(-sn);
      #pragma unroll
      for (int j = 4; j < 6; j++) {
          const int jb = j + 2;
          u64 a = srp[j], b = srp[jb];
          PMUL(srp[j],  CO,  a);  PMUL(sip[j],  NSN, b);
          PMUL(srp[jb], CO,  b);  PMUL(sip[jb], NSN, a);
      } }
    // CRX1: ctrl reg bit2, tgt reg bit1 -> (2,3) RE + (6,7) FULL
    { CBC(1)
      u64 CO = dup2(co), SN = dup2(sn), NSN = dup2(-sn);
      { u64 a = srp[2], b = srp[3];
        PMUL(srp[2], CO, a);  PMUL(sip[2], NSN, b);
        PMUL(srp[3], CO, b);  PMUL(sip[3], NSN, a); }
      { u64 ar = srp[6], br = srp[7], ai = sip[6], bi = sip[7];
        srp[6] = paxpby(CO, ar, SN,  bi);  sip[6] = paxpby(CO, ai, NSN, br);
        srp[7] = paxpby(CO, br, SN,  ai);  sip[7] = paxpby(CO, bi, NSN, ar); } }
    // CRX2: ctrl reg bit1, tgt reg bit0 (within pack): pack1 RE + packs 3,5,7 FULL
    { CBC(2)
      u64 CO = dup2(co), SN = dup2(sn), NSN = dup2(-sn);
      { float a0, a1; UP2(a0, a1, srp[1]);
        u64 rv; MK2(rv, a1, a0);
        PMUL(srp[1], CO, srp[1]);
        PMUL(sip[1], NSN, rv); }
      #pragma unroll
      for (int j = 3; j < 8; j += 2) {
          float r0, r1, i0, i1;
          UP2(r0, r1, srp[j]);  UP2(i0, i1, sip[j]);
          u64 rvr; MK2(rvr, r1, r0);
          u64 rvi; MK2(rvi, i1, i0);
          srp[j] = paxpby(CO, srp[j], SN,  rvi);
          sip[j] = paxpby(CO, sip[j], NSN, rvr);
      } }
    // CRX3: ctrl reg bit0 (odd slot), tgt lane bit3: scalar on odd halves
    { CBC(3)
      #pragma unroll
      for (int j = 0; j < 8; j++) {
          float e, o, ei, oi;
          UP2(e, o, srp[j]);  UP2(ei, oi, sip[j]);
          float pr = __shfl_xor_sync(FULL, o, 8);
          float pi = __shfl_xor_sync(FULL, oi, 8);
          float no  = fmaf(co, o,   sn * pi);
          float noi = fmaf(co, oi, -sn * pr);
          MK2(srp[j], e, no);  MK2(sip[j], ei, noi);
      } }
    // CRX4/5/6: lane-ctrl, lane-target (fold ctrl into coefficients)
    #define CRXL(CB, MASK) {                                                 \
        bool  g    = (lane >> (CB)) & 1;                                     \
        float co_e = g ? co : 1.0f;                                          \
        float sn_e = g ? sn : 0.0f;                                          \
        u64 COe = dup2(co_e), SNe = dup2(sn_e), NSNe = dup2(-sn_e);          \
        _Pragma("unroll")                                                    \
        for (int j = 0; j < 8; j++) {                                        \
            u64 pr = __shfl_xor_sync(FULL, srp[j], MASK);                    \
            u64 pi = __shfl_xor_sync(FULL, sip[j], MASK);                    \
            srp[j] = paxpby(COe, srp[j], SNe,  pi);                          \
            sip[j] = paxpby(COe, sip[j], NSNe, pr);                          \
        } }
    { CBC(4) CRXL(3, 4) }
    { CBC(5) CRXL(2, 2) }
    { CBC(6) CRXL(1, 1) }
    #undef CRXL
    // CRX7: ctrl lane bit0, tgt reg bit3 -> pack pairs (j, j+4)
    { CBC(7)
      bool  g    = lane & 1;
      float co_e = g ? co : 1.0f;
      float sn_e = g ? sn : 0.0f;
      u64 COe = dup2(co_e), SNe = dup2(sn_e), NSNe = dup2(-sn_e);
      #pragma unroll
      for (int j = 0; j < 4; j++) {
          u64 ar = srp[j], ai = sip[j], br = srp[j + 4], bi = sip[j + 4];
          srp[j]     = paxpby(COe, ar, SNe,  bi);
          sip[j]     = paxpby(COe, ai, NSNe, br);
          srp[j + 4] = paxpby(COe, br, SNe,  ai);
          sip[j + 4] = paxpby(COe, bi, NSNe, ar);
      } }
    // CRX8: ctrl reg bit3, tgt reg bit2 -> pack pairs (4,6),(5,7) FULL
    { CBC(8)
      u64 CO = dup2(co), SN = dup2(sn), NSN = dup2(-sn);
      #pragma unroll
      for (int j = 4; j < 6; j++) {
          const int jb = j + 2;
          u64 ar = srp[j], ai = sip[j], br = srp[jb], bi = sip[jb];
          srp[j]  = paxpby(CO, ar, SN,  bi);  sip[j]  = paxpby(CO, ai, NSN, br);
          srp[jb] = paxpby(CO, br, SN,  ai);  sip[jb] = paxpby(CO, bi, NSN, ar);
      } }
    // CRX9: ctrl reg bit2, tgt reg bit1 -> pack pairs (2,3),(6,7) FULL
    { CBC(9)
      u64 CO = dup2(co), SN = dup2(sn), NSN = dup2(-sn);
      #pragma unroll
      for (int j = 2; j < 8; j += 4) {
          const int jb = j + 1;
          u64 ar = srp[j], ai = sip[j], br = srp[jb], bi = sip[jb];
          srp[j]  = paxpby(CO, ar, SN,  bi);  sip[j]  = paxpby(CO, ai, NSN, br);
          srp[jb] = paxpby(CO, br, SN,  ai);  sip[jb] = paxpby(CO, bi, NSN, ar);
      } }
    #undef CBC

    // ---------------- Measurement + MLP ----------------
    // slot x accumulates even regs (qubit3 +), slot y odd regs (qubit3 -)
    u64 acc; { float z0 = 0.0f; MK2(acc, z0, z0); }
    #pragma unroll
    for (int j = 0; j < 8; j++) {
        PFMA(acc, srp[j], srp[j], acc);
        PFMA(acc, sip[j], sip[j], acc);
    }
    float S0, S1; UP2(S0, S1, acc);

    float f0  = S0 - S1;
    float tot = S0 + S1;
    float f1  = (lane & 1) ? -tot : tot;
    #pragma unroll
    for (int m = 8; m >= 1; m >>= 1) {
        f0 += __shfl_xor_sync(FULL, f0, m);
        f1 += __shfl_xor_sync(FULL, f1, m);
    }

    float contrib = 0.0f;
    if (lo < 10) {
        float z = fmaf(f0, __ldg(&w1[lo * 2 + 0]),
                  fmaf(f1, __ldg(&w1[lo * 2 + 1]), __ldg(&b1[lo])));
        contrib = tanhf(z) * __ldg(&w2[lo]);
    }
    #pragma unroll
    for (int m = 8; m >= 1; m >>= 1)
        contrib += __shfl_xor_sync(FULL, contrib, m);

    if (lo == 0) {
        const int e = e0 + (half >> 4);
        if (e < n_batch) {
            float z = contrib + __ldg(&b2[0]);
            out[e] = 1.0f / (1.0f + __expf(-z));
        }
    }
}

extern "C" void kernel_launch(void* const* d_in, const int* in_sizes, int n_in,
                              void* d_out, int out_size) {
    const float* x         = (const float*)d_in[0];
    const float* crx_theta = (const float*)d_in[1];
    const float* w1        = (const float*)d_in[2];
    const float* b1        = (const float*)d_in[3];
    const float* w2        = (const float*)d_in[4];
    const float* b2        = (const float*)d_in[5];
    float* out = (float*)d_out;

    const int n_batch = in_sizes[0] / 32;      // (B,4,8) -> B
    const int pairs   = (n_batch + 1) / 2;
    const int threads = 256;                   // 8 warps (16 elements) per block
    const int blocks  = (pairs + 7) / 8;
    vqc_kernel<<<blocks, threads>>>(x, crx_theta, w1, b1, w2, b2, out, n_batch);
}